// round 14
// baseline (speedup 1.0000x reference)
#include <cuda_runtime.h>
#include <math.h>

#define BN 8
#define CN 64
#define HN 256
#define WN 256
#define WINN 11
#define HP 246
#define TILE 16
#define TIN 26
#define NT2 256
#define GC 4
#define NGRP 16
#define HBS 20
#define XST 48

#define C1V 0.01f
#define C2V 0.09f

__device__ float d_gw[WINN];
__device__ float g_xc[BN * 3 * HN * WN];
__device__ float g_rowstats[BN * HN * 8];
__device__ float g_mean[BN * 3];
__device__ float g_rstd[BN * 3];
__device__ float g_part[BN * NT2 * 192];
__device__ float g_ssim[BN * 192];

__device__ __forceinline__ void cpa4(float* dst, const float* src) {
    unsigned s = (unsigned)__cvta_generic_to_shared(dst);
    asm volatile("cp.async.ca.shared.global [%0],[%1],4;" ::"r"(s), "l"(src));
}
__device__ __forceinline__ void cpa8(float* dst, const float* src) {
    unsigned s = (unsigned)__cvta_generic_to_shared(dst);
    asm volatile("cp.async.ca.shared.global [%0],[%1],8;" ::"r"(s), "l"(src));
}
#define CP_COMMIT asm volatile("cp.async.commit_group;")
#define CP_WAIT asm volatile("cp.async.wait_all;")

// ---------------------------------------------------------------------------
// Kernel A: per-pixel channel max/mean/min -> g_xc, per-row masked sums
// float4 vectorized; grid (HN/4, BN), block 256 = 64 float4-cols x 4 rows
// ---------------------------------------------------------------------------
__global__ void kA(const float* __restrict__ x, const int* __restrict__ mask) {
    const int b = blockIdx.y;
    const int tid = threadIdx.x;
    const int w4 = tid & 63;
    const int r = tid >> 6;
    const int h = blockIdx.x * 4 + r;

    const float4* xp = reinterpret_cast<const float4*>(x + (((size_t)b * CN) * HN + h) * WN) + w4;
    float4 mx = make_float4(-1e30f, -1e30f, -1e30f, -1e30f);
    float4 mn = make_float4(1e30f, 1e30f, 1e30f, 1e30f);
    float4 sm = make_float4(0.f, 0.f, 0.f, 0.f);
#pragma unroll 8
    for (int c = 0; c < CN; c++) {
        float4 v = xp[c * (HN * WN / 4)];
        mx.x = fmaxf(mx.x, v.x); mx.y = fmaxf(mx.y, v.y);
        mx.z = fmaxf(mx.z, v.z); mx.w = fmaxf(mx.w, v.w);
        mn.x = fminf(mn.x, v.x); mn.y = fminf(mn.y, v.y);
        mn.z = fminf(mn.z, v.z); mn.w = fminf(mn.w, v.w);
        sm.x += v.x; sm.y += v.y; sm.z += v.z; sm.w += v.w;
    }
    float4 me = make_float4(sm.x * (1.f / 64.f), sm.y * (1.f / 64.f),
                            sm.z * (1.f / 64.f), sm.w * (1.f / 64.f));
    {
        size_t base = (((size_t)b * 3) * HN + h) * WN + w4 * 4;
        *reinterpret_cast<float4*>(g_xc + base) = mx;
        *reinterpret_cast<float4*>(g_xc + base + (size_t)HN * WN) = me;
        *reinterpret_cast<float4*>(g_xc + base + 2 * (size_t)HN * WN) = mn;
    }

    int4 mi = *reinterpret_cast<const int4*>(mask + ((size_t)b * HN + h) * WN + w4 * 4);
    float m0 = (float)mi.x, m1 = (float)mi.y, m2 = (float)mi.z, m3 = (float)mi.w;
    float vals[7];
    vals[0] = m0 + m1 + m2 + m3;
    vals[1] = mx.x * m0 + mx.y * m1 + mx.z * m2 + mx.w * m3;
    vals[2] = me.x * m0 + me.y * m1 + me.z * m2 + me.w * m3;
    vals[3] = mn.x * m0 + mn.y * m1 + mn.z * m2 + mn.w * m3;
    vals[4] = mx.x * mx.x * m0 + mx.y * mx.y * m1 + mx.z * mx.z * m2 + mx.w * mx.w * m3;
    vals[5] = me.x * me.x * m0 + me.y * me.y * m1 + me.z * me.z * m2 + me.w * me.w * m3;
    vals[6] = mn.x * mn.x * m0 + mn.y * mn.y * m1 + mn.z * mn.z * m2 + mn.w * mn.w * m3;

    __shared__ float red[8][7];
    int lane = tid & 31, wid = tid >> 5;  // warps 2r, 2r+1 belong to row r
#pragma unroll
    for (int i = 0; i < 7; i++) {
        float v = vals[i];
#pragma unroll
        for (int o = 16; o; o >>= 1) v += __shfl_xor_sync(0xffffffffu, v, o);
        if (lane == 0) red[wid][i] = v;
    }
    __syncthreads();
    if (tid < 28) {
        int rr = tid / 7, i = tid - rr * 7;
        g_rowstats[((size_t)b * HN + blockIdx.x * 4 + rr) * 8 + i] =
            red[2 * rr][i] + red[2 * rr + 1][i];
    }
}

// ---------------------------------------------------------------------------
// Kernel A2: reduce row stats -> mean, rstd (fp64); also computes d_gw
// ---------------------------------------------------------------------------
__global__ void kA2() {
    int b = blockIdx.x, t = threadIdx.x;
    if (t == 0) {
        double g[WINN];
        double s = 0.0;
        for (int i = 0; i < WINN; i++) {
            double d = (double)(i - WINN / 2);
            g[i] = exp(-d * d / (2.0 * 1.5 * 1.5));
            s += g[i];
        }
        for (int i = 0; i < WINN; i++) d_gw[i] = (float)(g[i] / s);
    }
    __shared__ double sred[8][7];
    double v[7];
#pragma unroll
    for (int i = 0; i < 7; i++) v[i] = (double)g_rowstats[((size_t)b * HN + t) * 8 + i];
    int lane = t & 31, wid = t >> 5;
#pragma unroll
    for (int i = 0; i < 7; i++) {
        double d = v[i];
#pragma unroll
        for (int o = 16; o; o >>= 1) d += __shfl_xor_sync(0xffffffffu, d, o);
        if (lane == 0) sred[wid][i] = d;
    }
    __syncthreads();
    if (t == 0) {
        double s[7];
#pragma unroll
        for (int i = 0; i < 7; i++) {
            double a = 0.0;
            for (int k = 0; k < 8; k++) a += sred[k][i];
            s[i] = a;
        }
        double n = s[0];
        for (int a = 0; a < 3; a++) {
            double mean = s[1 + a] / n;
            double var = (s[4 + a] - n * mean * mean) / (n - 1.0);
            g_mean[b * 3 + a] = (float)mean;
            g_rstd[b * 3 + a] = (float)(1.0 / sqrt(var));
        }
    }
}

// ---------------------------------------------------------------------------
// Kernel C: fused separable-blur SSIM. Phase-1 j-pair + LDS.64 (stride 48),
// all-thread cpa8 prefetch (R8 scheme), hb stride 20 (conflict-free scalar
// phase 2), fast division. grid (16,16,BN), block 256, 2 CTAs/SM.
// ---------------------------------------------------------------------------
#define XF(a, r, cc) xf_s[((a) * TIN + (r)) * XST + (cc)]
#define HB(r, j, sc) hb[((r) * TILE + (j)) * HBS + (sc)]
#define HFB(r, j, q) hfb[((r) * TILE + (j)) * 6 + (q)]
#define SFS(py, px, q) SfS[((py) * TILE + (px)) * 6 + (q)]

#define XFN (3 * TIN * XST)
#define XSBUF (GC * TIN * XST)
#define SMEM_TOT ((XFN + 2 * XSBUF + TIN * TILE * HBS + TILE * TILE * 6 + 192) * 4)

__device__ __forceinline__ void prefetch_group(const float* __restrict__ xb, float* __restrict__ buf,
                                               int c0, int ox, int oy, int tid, bool interior) {
    if (interior) {
        for (int idx = tid; idx < GC * TIN * 13; idx += 256) {
            int c = idx / (TIN * 13);
            int rem = idx - c * (TIN * 13);
            int rr = rem / 13, q = rem - rr * 13;
            cpa8(buf + (c * TIN + rr) * XST + 2 * q,
                 xb + (((size_t)(c0 + c)) * HN + (oy + rr)) * WN + ox + 2 * q);
        }
    } else {
        for (int idx = tid; idx < GC * TIN * TIN; idx += 256) {
            int c = idx / (TIN * TIN);
            int rem = idx - c * (TIN * TIN);
            int rr = rem / TIN, cc = rem - rr * TIN;
            int gy = min(oy + rr, HN - 1), gx = min(ox + cc, WN - 1);
            cpa4(buf + (c * TIN + rr) * XST + cc,
                 xb + (((size_t)(c0 + c)) * HN + gy) * WN + gx);
        }
    }
    CP_COMMIT;
}

__global__ __launch_bounds__(256, 2) void kC(const float* __restrict__ x,
                                             const int* __restrict__ mask) {
    extern __shared__ float smem[];
    float* xf_s = smem;                       // [3][26][48]
    float* xs0 = xf_s + XFN;                  // 2 x [4][26][48]
    float* hb = xs0 + 2 * XSBUF;              // [26][16][20]
    float* SfS = hb + TIN * TILE * HBS;       // [16][16][6]
    float* s_acc = SfS + TILE * TILE * 6;     // [192]
    float* hfb = xs0 + XSBUF;                 // aliases xs buffer 1 (dead before g=1 prefetch)

    const int tx = blockIdx.x, ty = blockIdx.y, b = blockIdx.z;
    const int ox = tx * TILE, oy = ty * TILE;
    const int tid = threadIdx.x;
    const bool interior = (ox + TIN <= WN) && (oy + TIN <= HN);
    const float* xb = x + (size_t)b * CN * HN * WN;

    float gw[WINN];
#pragma unroll
    for (int i = 0; i < WINN; i++) gw[i] = d_gw[i];

    if (tid < 192) s_acc[tid] = 0.f;

    // kick off prefetch of channel group 0 into xs buffer 0
    prefetch_group(xb, xs0, 0, ox, oy, tid, interior);

    // load xf tile: xf = (xc - mean) * rstd * mask
    {
        float mean[3], rstd[3];
#pragma unroll
        for (int a = 0; a < 3; a++) {
            mean[a] = g_mean[b * 3 + a];
            rstd[a] = g_rstd[b * 3 + a];
        }
        for (int idx = tid; idx < 3 * TIN * TIN; idx += 256) {
            int a = idx / (TIN * TIN);
            int rem = idx - a * (TIN * TIN);
            int rr = rem / TIN, cc = rem - rr * TIN;
            int gy = min(oy + rr, HN - 1), gx = min(ox + cc, WN - 1);
            float mc = (float)mask[((size_t)b * HN + gy) * WN + gx];
            float v = g_xc[(((size_t)b * 3 + a) * HN + gy) * WN + gx];
            XF(a, rr, cc) = (v - mean[a]) * rstd[a] * mc;
        }
    }
    __syncthreads();

    // phase0: horizontal conv of xf, xf^2 -> hfb (aliases xs buf 1)
    for (int p = tid; p < TIN * TILE; p += 256) {
        int r = p / TILE, j = p - (p / TILE) * TILE;
        float hf[3] = {0, 0, 0}, hff[3] = {0, 0, 0};
#pragma unroll
        for (int k = 0; k < WINN; k++) {
            float wk = gw[k];
#pragma unroll
            for (int a = 0; a < 3; a++) {
                float v = XF(a, r, j + k);
                float t = wk * v;
                hf[a] += t;
                hff[a] = fmaf(t, v, hff[a]);
            }
        }
#pragma unroll
        for (int a = 0; a < 3; a++) {
            HFB(r, j, a) = hf[a];
            HFB(r, j, 3 + a) = hff[a];
        }
    }
    __syncthreads();

    // phase0b: vertical -> Sf, Sff per output pixel
    {
        int px = tid & 15, py = tid >> 4;
        float s[6] = {0, 0, 0, 0, 0, 0};
#pragma unroll
        for (int i = 0; i < WINN; i++) {
            float vi = gw[i];
#pragma unroll
            for (int q = 0; q < 6; q++) s[q] = fmaf(vi, HFB(py + i, px, q), s[q]);
        }
#pragma unroll
        for (int q = 0; q < 6; q++) SFS(py, px, q) = s[q];
    }
    CP_WAIT;
    __syncthreads();  // group-0 tile + SfS visible; hfb dead -> buf1 reusable

    const int c_l = tid & 3;
    const int pxq = (tid >> 2) & 15;
    const int slot = tid >> 6;
    const bool vx = (ox + pxq) < HP;

    // phase-1 item: (r, jp) with j = 2*jp; 208 items on tids 0..207
    const int r1 = tid >> 3;
    const int j1 = (tid & 7) * 2;

    for (int g = 0; g < NGRP; g++) {
        float* xs = xs0 + (g & 1) * XSBUF;
        if (g + 1 < NGRP)
            prefetch_group(xb, xs0 + ((g + 1) & 1) * XSBUF, (g + 1) * GC, ox, oy, tid, interior);
        int c0 = g * GC;

        // phase1: horizontal pass, j-pair register blocking, float2 loads -> hb
        if (tid < 208) {
            const float* xfr = xf_s + r1 * XST + j1;
            const float* xsr = xs + r1 * XST + j1;
            float hx0[4] = {0, 0, 0, 0}, hx1[4] = {0, 0, 0, 0};
            float hxx0[4] = {0, 0, 0, 0}, hxx1[4] = {0, 0, 0, 0};
            float cr0[12], cr1[12];
#pragma unroll
            for (int q = 0; q < 12; q++) {
                cr0[q] = 0.f;
                cr1[q] = 0.f;
            }
#pragma unroll
            for (int kk = 0; kk < 6; kk++) {
                const float2 f0 = *reinterpret_cast<const float2*>(xfr + 2 * kk);
                const float2 f1 = *reinterpret_cast<const float2*>(xfr + TIN * XST + 2 * kk);
                const float2 f2 = *reinterpret_cast<const float2*>(xfr + 2 * TIN * XST + 2 * kk);
                float2 xv[GC];
#pragma unroll
                for (int c = 0; c < GC; c++)
                    xv[c] = *reinterpret_cast<const float2*>(xsr + c * TIN * XST + 2 * kk);
                {
                    const int k = 2 * kk;
                    const float w0 = gw[k];
#pragma unroll
                    for (int c = 0; c < GC; c++) {
                        const float t0 = w0 * xv[c].x;
                        hx0[c] += t0;
                        hxx0[c] = fmaf(t0, xv[c].x, hxx0[c]);
                        cr0[c] = fmaf(f0.x, t0, cr0[c]);
                        cr0[4 + c] = fmaf(f1.x, t0, cr0[4 + c]);
                        cr0[8 + c] = fmaf(f2.x, t0, cr0[8 + c]);
                    }
                    if (k > 0) {
                        const float w1 = gw[k - 1];
#pragma unroll
                        for (int c = 0; c < GC; c++) {
                            const float t1 = w1 * xv[c].x;
                            hx1[c] += t1;
                            hxx1[c] = fmaf(t1, xv[c].x, hxx1[c]);
                            cr1[c] = fmaf(f0.x, t1, cr1[c]);
                            cr1[4 + c] = fmaf(f1.x, t1, cr1[4 + c]);
                            cr1[8 + c] = fmaf(f2.x, t1, cr1[8 + c]);
                        }
                    }
                }
                {
                    const int k = 2 * kk + 1;
                    if (k < 11) {
                        const float w0 = gw[k];
#pragma unroll
                        for (int c = 0; c < GC; c++) {
                            const float t0 = w0 * xv[c].y;
                            hx0[c] += t0;
                            hxx0[c] = fmaf(t0, xv[c].y, hxx0[c]);
                            cr0[c] = fmaf(f0.y, t0, cr0[c]);
                            cr0[4 + c] = fmaf(f1.y, t0, cr0[4 + c]);
                            cr0[8 + c] = fmaf(f2.y, t0, cr0[8 + c]);
                        }
                    }
                    {
                        const float w1 = gw[k - 1];
#pragma unroll
                        for (int c = 0; c < GC; c++) {
                            const float t1 = w1 * xv[c].y;
                            hx1[c] += t1;
                            hxx1[c] = fmaf(t1, xv[c].y, hxx1[c]);
                            cr1[c] = fmaf(f0.y, t1, cr1[c]);
                            cr1[4 + c] = fmaf(f1.y, t1, cr1[4 + c]);
                            cr1[8 + c] = fmaf(f2.y, t1, cr1[8 + c]);
                        }
                    }
                }
            }
            float4* d0 = reinterpret_cast<float4*>(&HB(r1, j1, 0));
            d0[0] = make_float4(hx0[0], hx0[1], hx0[2], hx0[3]);
            d0[1] = make_float4(hxx0[0], hxx0[1], hxx0[2], hxx0[3]);
            d0[2] = make_float4(cr0[0], cr0[1], cr0[2], cr0[3]);
            d0[3] = make_float4(cr0[4], cr0[5], cr0[6], cr0[7]);
            d0[4] = make_float4(cr0[8], cr0[9], cr0[10], cr0[11]);
            float4* d1 = reinterpret_cast<float4*>(&HB(r1, j1 + 1, 0));
            d1[0] = make_float4(hx1[0], hx1[1], hx1[2], hx1[3]);
            d1[1] = make_float4(hxx1[0], hxx1[1], hxx1[2], hxx1[3]);
            d1[2] = make_float4(cr1[0], cr1[1], cr1[2], cr1[3]);
            d1[3] = make_float4(cr1[4], cr1[5], cr1[6], cr1[7]);
            d1[4] = make_float4(cr1[8], cr1[9], cr1[10], cr1[11]);
        }
        __syncthreads();

        // phase2: vertical pass with register accumulators + ssim
        float acc[4][5];
#pragma unroll
        for (int li = 0; li < 4; li++)
#pragma unroll
            for (int s = 0; s < 5; s++) acc[li][s] = 0.f;

        const int rbase = slot * 4;
#pragma unroll
        for (int rr = 0; rr < 14; rr++) {
            int r = rbase + rr;
            float v0 = HB(r, pxq, 0 * 4 + c_l);
            float v1 = HB(r, pxq, 1 * 4 + c_l);
            float v2 = HB(r, pxq, 2 * 4 + c_l);
            float v3 = HB(r, pxq, 3 * 4 + c_l);
            float v4 = HB(r, pxq, 4 * 4 + c_l);
#pragma unroll
            for (int li = 0; li < 4; li++) {
                int kk = rr - li;
                if (kk >= 0 && kk < WINN) {
                    float vi = gw[kk];
                    acc[li][0] = fmaf(vi, v0, acc[li][0]);
                    acc[li][1] = fmaf(vi, v1, acc[li][1]);
                    acc[li][2] = fmaf(vi, v2, acc[li][2]);
                    acc[li][3] = fmaf(vi, v3, acc[li][3]);
                    acc[li][4] = fmaf(vi, v4, acc[li][4]);
                }
            }
        }

        float sacc[3] = {0.f, 0.f, 0.f};
#pragma unroll
        for (int li = 0; li < 4; li++) {
            int py = rbase + li;
            if (vx && (oy + py) < HP) {
                float mu2 = acc[li][0];
                float s2 = acc[li][1] - mu2 * mu2;
#pragma unroll
                for (int a = 0; a < 3; a++) {
                    float mu1 = SFS(py, pxq, a);
                    float s1 = SFS(py, pxq, 3 + a) - mu1 * mu1;
                    float s12 = acc[li][2 + a] - mu1 * mu2;
                    float num = (2.f * mu1 * mu2 + C1V) * (2.f * s12 + C2V);
                    float den = (mu1 * mu1 + mu2 * mu2 + C1V) * (s1 + s2 + C2V);
                    sacc[a] += __fdividef(num, den);
                }
            }
        }
#pragma unroll
        for (int a = 0; a < 3; a++) {
            float v = sacc[a];
            v += __shfl_xor_sync(0xffffffffu, v, 4);
            v += __shfl_xor_sync(0xffffffffu, v, 8);
            v += __shfl_xor_sync(0xffffffffu, v, 16);
            if ((tid & 31) < 4) atomicAdd(&s_acc[a * 64 + c0 + c_l], v);
        }
        CP_WAIT;          // next group's tile arrived (this thread's copies)
        __syncthreads();  // visible to all; hb free for overwrite
    }

    if (tid < 192)
        g_part[((size_t)b * NT2 + (ty * 16 + tx)) * 192 + tid] = s_acc[tid];
}

// ---------------------------------------------------------------------------
// Kernel D1: parallel tile reduction -> g_ssim + ssim_info output
// grid (192, BN), block 256: one block per (b, stat)
// ---------------------------------------------------------------------------
__global__ void kD1(float* __restrict__ out) {
    const int o = blockIdx.x;   // 0..191
    const int b = blockIdx.y;
    const int t = threadIdx.x;  // tile index 0..255
    float v = g_part[((size_t)b * NT2 + t) * 192 + o];
    __shared__ float red[8];
    int lane = t & 31, wid = t >> 5;
#pragma unroll
    for (int off = 16; off; off >>= 1) v += __shfl_xor_sync(0xffffffffu, v, off);
    if (lane == 0) red[wid] = v;
    __syncthreads();
    if (t == 0) {
        float s = 0.f;
#pragma unroll
        for (int k = 0; k < 8; k++) s += red[k];
        float si = s * (1.0f / (246.0f * 246.0f));
        g_ssim[b * 192 + o] = si;
        out[512 + b * 192 + o] = si;  // ssim_info after h
    }
}

// ---------------------------------------------------------------------------
// Kernel D2: conv over C; MLP head. grid BN, block 192
// ---------------------------------------------------------------------------
__global__ void kD2(const float* __restrict__ conv_w, const float* __restrict__ w1,
                    const float* __restrict__ b1, const float* __restrict__ w2,
                    const float* __restrict__ b2, float* __restrict__ out) {
    int b = blockIdx.x, t = threadIdx.x;
    __shared__ float ss[192];
    __shared__ float h0[64], h1[64];
    ss[t] = g_ssim[b * 192 + t];
    __syncthreads();
    if (t < 64) {
        float acc = 0.f;
#pragma unroll
        for (int a = 0; a < 3; a++)
#pragma unroll
            for (int kh = 0; kh < 3; kh++) {
                int cc = t + kh - 1;
                if (cc >= 0 && cc < 64) acc = fmaf(ss[a * 64 + cc], conv_w[a * 3 + kh], acc);
            }
        h0[t] = fmaxf(acc, 0.f);
    }
    __syncthreads();
    if (t < 64) {
        float acc = b1[t];
#pragma unroll 8
        for (int k = 0; k < 64; k++) acc = fmaf(h0[k], w1[t * 64 + k], acc);
        h1[t] = fmaxf(acc, 0.f);
    }
    __syncthreads();
    if (t < 64) {
        float acc = b2[t];
#pragma unroll 8
        for (int k = 0; k < 64; k++) acc = fmaf(h1[k], w2[t * 64 + k], acc);
        out[b * 64 + t] = __fdividef(1.f, 1.f + __expf(-acc));
    }
}

// ---------------------------------------------------------------------------
extern "C" void kernel_launch(void* const* d_in, const int* in_sizes, int n_in,
                              void* d_out, int out_size) {
    const float* x = (const float*)d_in[0];
    const int* mask = (const int*)d_in[1];
    const float* conv_w = (const float*)d_in[2];
    const float* w1 = (const float*)d_in[3];
    const float* b1 = (const float*)d_in[4];
    const float* w2 = (const float*)d_in[5];
    const float* b2 = (const float*)d_in[6];
    float* out = (float*)d_out;

    cudaFuncSetAttribute(kC, cudaFuncAttributeMaxDynamicSharedMemorySize, SMEM_TOT);

    kA<<<dim3(HN / 4, BN), 256>>>(x, mask);
    kA2<<<BN, 256>>>();
    kC<<<dim3(16, 16, BN), 256, SMEM_TOT>>>(x, mask);
    kD1<<<dim3(192, BN), 256>>>(out);
    kD2<<<BN, 192>>>(conv_w, w1, b1, w2, b2, out);
}

// round 15
// speedup vs baseline: 1.0382x; 1.0382x over previous
#include <cuda_runtime.h>
#include <math.h>

#define BN 8
#define CN 64
#define HN 256
#define WN 256
#define WINN 11
#define HP 246
#define TILE 16
#define TIN 26
#define NT2 256
#define GC 4
#define NGRP 16
#define HBS 20
#define XST 48

#define C1V 0.01f
#define C2V 0.09f

__device__ float d_gw[WINN];
__device__ float g_xc[BN * 3 * HN * WN];
__device__ float g_rowstats[BN * HN * 8];
__device__ float g_mean[BN * 3];
__device__ float g_rstd[BN * 3];
__device__ float g_part[BN * NT2 * 192];

__device__ __forceinline__ void cpa4(float* dst, const float* src) {
    unsigned s = (unsigned)__cvta_generic_to_shared(dst);
    asm volatile("cp.async.ca.shared.global [%0],[%1],4;" ::"r"(s), "l"(src));
}
__device__ __forceinline__ void cpa8(float* dst, const float* src) {
    unsigned s = (unsigned)__cvta_generic_to_shared(dst);
    asm volatile("cp.async.ca.shared.global [%0],[%1],8;" ::"r"(s), "l"(src));
}
#define CP_COMMIT asm volatile("cp.async.commit_group;")
#define CP_WAIT asm volatile("cp.async.wait_all;")

// ---------------------------------------------------------------------------
// Kernel A: per-pixel channel max/mean/min -> g_xc, per-row masked sums
// float4 vectorized; grid (HN/4, BN), block 256 = 64 float4-cols x 4 rows
// ---------------------------------------------------------------------------
__global__ void kA(const float* __restrict__ x, const int* __restrict__ mask) {
    const int b = blockIdx.y;
    const int tid = threadIdx.x;
    const int w4 = tid & 63;
    const int r = tid >> 6;
    const int h = blockIdx.x * 4 + r;

    const float4* xp = reinterpret_cast<const float4*>(x + (((size_t)b * CN) * HN + h) * WN) + w4;
    float4 mx = make_float4(-1e30f, -1e30f, -1e30f, -1e30f);
    float4 mn = make_float4(1e30f, 1e30f, 1e30f, 1e30f);
    float4 sm = make_float4(0.f, 0.f, 0.f, 0.f);
#pragma unroll 8
    for (int c = 0; c < CN; c++) {
        float4 v = xp[c * (HN * WN / 4)];
        mx.x = fmaxf(mx.x, v.x); mx.y = fmaxf(mx.y, v.y);
        mx.z = fmaxf(mx.z, v.z); mx.w = fmaxf(mx.w, v.w);
        mn.x = fminf(mn.x, v.x); mn.y = fminf(mn.y, v.y);
        mn.z = fminf(mn.z, v.z); mn.w = fminf(mn.w, v.w);
        sm.x += v.x; sm.y += v.y; sm.z += v.z; sm.w += v.w;
    }
    float4 me = make_float4(sm.x * (1.f / 64.f), sm.y * (1.f / 64.f),
                            sm.z * (1.f / 64.f), sm.w * (1.f / 64.f));
    {
        size_t base = (((size_t)b * 3) * HN + h) * WN + w4 * 4;
        *reinterpret_cast<float4*>(g_xc + base) = mx;
        *reinterpret_cast<float4*>(g_xc + base + (size_t)HN * WN) = me;
        *reinterpret_cast<float4*>(g_xc + base + 2 * (size_t)HN * WN) = mn;
    }

    int4 mi = *reinterpret_cast<const int4*>(mask + ((size_t)b * HN + h) * WN + w4 * 4);
    float m0 = (float)mi.x, m1 = (float)mi.y, m2 = (float)mi.z, m3 = (float)mi.w;
    float vals[7];
    vals[0] = m0 + m1 + m2 + m3;
    vals[1] = mx.x * m0 + mx.y * m1 + mx.z * m2 + mx.w * m3;
    vals[2] = me.x * m0 + me.y * m1 + me.z * m2 + me.w * m3;
    vals[3] = mn.x * m0 + mn.y * m1 + mn.z * m2 + mn.w * m3;
    vals[4] = mx.x * mx.x * m0 + mx.y * mx.y * m1 + mx.z * mx.z * m2 + mx.w * mx.w * m3;
    vals[5] = me.x * me.x * m0 + me.y * me.y * m1 + me.z * me.z * m2 + me.w * me.w * m3;
    vals[6] = mn.x * mn.x * m0 + mn.y * mn.y * m1 + mn.z * mn.z * m2 + mn.w * mn.w * m3;

    __shared__ float red[8][7];
    int lane = tid & 31, wid = tid >> 5;  // warps 2r, 2r+1 belong to row r
#pragma unroll
    for (int i = 0; i < 7; i++) {
        float v = vals[i];
#pragma unroll
        for (int o = 16; o; o >>= 1) v += __shfl_xor_sync(0xffffffffu, v, o);
        if (lane == 0) red[wid][i] = v;
    }
    __syncthreads();
    if (tid < 28) {
        int rr = tid / 7, i = tid - rr * 7;
        g_rowstats[((size_t)b * HN + blockIdx.x * 4 + rr) * 8 + i] =
            red[2 * rr][i] + red[2 * rr + 1][i];
    }
}

// ---------------------------------------------------------------------------
// Kernel A2: reduce row stats -> mean, rstd (fp64); also computes d_gw
// ---------------------------------------------------------------------------
__global__ void kA2() {
    int b = blockIdx.x, t = threadIdx.x;
    if (t == 0) {
        double g[WINN];
        double s = 0.0;
        for (int i = 0; i < WINN; i++) {
            double d = (double)(i - WINN / 2);
            g[i] = exp(-d * d / (2.0 * 1.5 * 1.5));
            s += g[i];
        }
        for (int i = 0; i < WINN; i++) d_gw[i] = (float)(g[i] / s);
    }
    __shared__ double sred[8][7];
    double v[7];
#pragma unroll
    for (int i = 0; i < 7; i++) v[i] = (double)g_rowstats[((size_t)b * HN + t) * 8 + i];
    int lane = t & 31, wid = t >> 5;
#pragma unroll
    for (int i = 0; i < 7; i++) {
        double d = v[i];
#pragma unroll
        for (int o = 16; o; o >>= 1) d += __shfl_xor_sync(0xffffffffu, d, o);
        if (lane == 0) sred[wid][i] = d;
    }
    __syncthreads();
    if (t == 0) {
        double s[7];
#pragma unroll
        for (int i = 0; i < 7; i++) {
            double a = 0.0;
            for (int k = 0; k < 8; k++) a += sred[k][i];
            s[i] = a;
        }
        double n = s[0];
        for (int a = 0; a < 3; a++) {
            double mean = s[1 + a] / n;
            double var = (s[4 + a] - n * mean * mean) / (n - 1.0);
            g_mean[b * 3 + a] = (float)mean;
            g_rstd[b * 3 + a] = (float)(1.0 / sqrt(var));
        }
    }
}

// ---------------------------------------------------------------------------
// Kernel C: fused separable-blur SSIM. Phase-1 j-pair + LDS.64 (stride 48),
// all-thread cpa8 prefetch (R8 scheme), hb stride 20 (conflict-free scalar
// phase 2), fast division. grid (16,16,BN), block 256, 2 CTAs/SM.
// ---------------------------------------------------------------------------
#define XF(a, r, cc) xf_s[((a) * TIN + (r)) * XST + (cc)]
#define HB(r, j, sc) hb[((r) * TILE + (j)) * HBS + (sc)]
#define HFB(r, j, q) hfb[((r) * TILE + (j)) * 6 + (q)]
#define SFS(py, px, q) SfS[((py) * TILE + (px)) * 6 + (q)]

#define XFN (3 * TIN * XST)
#define XSBUF (GC * TIN * XST)
#define SMEM_TOT ((XFN + 2 * XSBUF + TIN * TILE * HBS + TILE * TILE * 6 + 192) * 4)

__device__ __forceinline__ void prefetch_group(const float* __restrict__ xb, float* __restrict__ buf,
                                               int c0, int ox, int oy, int tid, bool interior) {
    if (interior) {
        for (int idx = tid; idx < GC * TIN * 13; idx += 256) {
            int c = idx / (TIN * 13);
            int rem = idx - c * (TIN * 13);
            int rr = rem / 13, q = rem - rr * 13;
            cpa8(buf + (c * TIN + rr) * XST + 2 * q,
                 xb + (((size_t)(c0 + c)) * HN + (oy + rr)) * WN + ox + 2 * q);
        }
    } else {
        for (int idx = tid; idx < GC * TIN * TIN; idx += 256) {
            int c = idx / (TIN * TIN);
            int rem = idx - c * (TIN * TIN);
            int rr = rem / TIN, cc = rem - rr * TIN;
            int gy = min(oy + rr, HN - 1), gx = min(ox + cc, WN - 1);
            cpa4(buf + (c * TIN + rr) * XST + cc,
                 xb + (((size_t)(c0 + c)) * HN + gy) * WN + gx);
        }
    }
    CP_COMMIT;
}

__global__ __launch_bounds__(256, 2) void kC(const float* __restrict__ x,
                                             const int* __restrict__ mask) {
    extern __shared__ float smem[];
    float* xf_s = smem;                       // [3][26][48]
    float* xs0 = xf_s + XFN;                  // 2 x [4][26][48]
    float* hb = xs0 + 2 * XSBUF;              // [26][16][20]
    float* SfS = hb + TIN * TILE * HBS;       // [16][16][6]
    float* s_acc = SfS + TILE * TILE * 6;     // [192]
    float* hfb = xs0 + XSBUF;                 // aliases xs buffer 1 (dead before g=1 prefetch)

    const int tx = blockIdx.x, ty = blockIdx.y, b = blockIdx.z;
    const int ox = tx * TILE, oy = ty * TILE;
    const int tid = threadIdx.x;
    const bool interior = (ox + TIN <= WN) && (oy + TIN <= HN);
    const float* xb = x + (size_t)b * CN * HN * WN;

    float gw[WINN];
#pragma unroll
    for (int i = 0; i < WINN; i++) gw[i] = d_gw[i];

    if (tid < 192) s_acc[tid] = 0.f;

    // kick off prefetch of channel group 0 into xs buffer 0
    prefetch_group(xb, xs0, 0, ox, oy, tid, interior);

    // load xf tile: xf = (xc - mean) * rstd * mask
    {
        float mean[3], rstd[3];
#pragma unroll
        for (int a = 0; a < 3; a++) {
            mean[a] = g_mean[b * 3 + a];
            rstd[a] = g_rstd[b * 3 + a];
        }
        for (int idx = tid; idx < 3 * TIN * TIN; idx += 256) {
            int a = idx / (TIN * TIN);
            int rem = idx - a * (TIN * TIN);
            int rr = rem / TIN, cc = rem - rr * TIN;
            int gy = min(oy + rr, HN - 1), gx = min(ox + cc, WN - 1);
            float mc = (float)mask[((size_t)b * HN + gy) * WN + gx];
            float v = g_xc[(((size_t)b * 3 + a) * HN + gy) * WN + gx];
            XF(a, rr, cc) = (v - mean[a]) * rstd[a] * mc;
        }
    }
    __syncthreads();

    // phase0: horizontal conv of xf, xf^2 -> hfb (aliases xs buf 1)
    for (int p = tid; p < TIN * TILE; p += 256) {
        int r = p / TILE, j = p - (p / TILE) * TILE;
        float hf[3] = {0, 0, 0}, hff[3] = {0, 0, 0};
#pragma unroll
        for (int k = 0; k < WINN; k++) {
            float wk = gw[k];
#pragma unroll
            for (int a = 0; a < 3; a++) {
                float v = XF(a, r, j + k);
                float t = wk * v;
                hf[a] += t;
                hff[a] = fmaf(t, v, hff[a]);
            }
        }
#pragma unroll
        for (int a = 0; a < 3; a++) {
            HFB(r, j, a) = hf[a];
            HFB(r, j, 3 + a) = hff[a];
        }
    }
    __syncthreads();

    // phase0b: vertical -> Sf, Sff per output pixel
    {
        int px = tid & 15, py = tid >> 4;
        float s[6] = {0, 0, 0, 0, 0, 0};
#pragma unroll
        for (int i = 0; i < WINN; i++) {
            float vi = gw[i];
#pragma unroll
            for (int q = 0; q < 6; q++) s[q] = fmaf(vi, HFB(py + i, px, q), s[q]);
        }
#pragma unroll
        for (int q = 0; q < 6; q++) SFS(py, px, q) = s[q];
    }
    CP_WAIT;
    __syncthreads();  // group-0 tile + SfS visible; hfb dead -> buf1 reusable

    const int c_l = tid & 3;
    const int pxq = (tid >> 2) & 15;
    const int slot = tid >> 6;
    const bool vx = (ox + pxq) < HP;

    // phase-1 item: (r, jp) with j = 2*jp; 208 items on tids 0..207
    const int r1 = tid >> 3;
    const int j1 = (tid & 7) * 2;

    for (int g = 0; g < NGRP; g++) {
        float* xs = xs0 + (g & 1) * XSBUF;
        if (g + 1 < NGRP)
            prefetch_group(xb, xs0 + ((g + 1) & 1) * XSBUF, (g + 1) * GC, ox, oy, tid, interior);
        int c0 = g * GC;

        // phase1: horizontal pass, j-pair register blocking, float2 loads -> hb
        if (tid < 208) {
            const float* xfr = xf_s + r1 * XST + j1;
            const float* xsr = xs + r1 * XST + j1;
            float hx0[4] = {0, 0, 0, 0}, hx1[4] = {0, 0, 0, 0};
            float hxx0[4] = {0, 0, 0, 0}, hxx1[4] = {0, 0, 0, 0};
            float cr0[12], cr1[12];
#pragma unroll
            for (int q = 0; q < 12; q++) {
                cr0[q] = 0.f;
                cr1[q] = 0.f;
            }
#pragma unroll
            for (int kk = 0; kk < 6; kk++) {
                const float2 f0 = *reinterpret_cast<const float2*>(xfr + 2 * kk);
                const float2 f1 = *reinterpret_cast<const float2*>(xfr + TIN * XST + 2 * kk);
                const float2 f2 = *reinterpret_cast<const float2*>(xfr + 2 * TIN * XST + 2 * kk);
                float2 xv[GC];
#pragma unroll
                for (int c = 0; c < GC; c++)
                    xv[c] = *reinterpret_cast<const float2*>(xsr + c * TIN * XST + 2 * kk);
                {
                    const int k = 2 * kk;
                    const float w0 = gw[k];
#pragma unroll
                    for (int c = 0; c < GC; c++) {
                        const float t0 = w0 * xv[c].x;
                        hx0[c] += t0;
                        hxx0[c] = fmaf(t0, xv[c].x, hxx0[c]);
                        cr0[c] = fmaf(f0.x, t0, cr0[c]);
                        cr0[4 + c] = fmaf(f1.x, t0, cr0[4 + c]);
                        cr0[8 + c] = fmaf(f2.x, t0, cr0[8 + c]);
                    }
                    if (k > 0) {
                        const float w1 = gw[k - 1];
#pragma unroll
                        for (int c = 0; c < GC; c++) {
                            const float t1 = w1 * xv[c].x;
                            hx1[c] += t1;
                            hxx1[c] = fmaf(t1, xv[c].x, hxx1[c]);
                            cr1[c] = fmaf(f0.x, t1, cr1[c]);
                            cr1[4 + c] = fmaf(f1.x, t1, cr1[4 + c]);
                            cr1[8 + c] = fmaf(f2.x, t1, cr1[8 + c]);
                        }
                    }
                }
                {
                    const int k = 2 * kk + 1;
                    if (k < 11) {
                        const float w0 = gw[k];
#pragma unroll
                        for (int c = 0; c < GC; c++) {
                            const float t0 = w0 * xv[c].y;
                            hx0[c] += t0;
                            hxx0[c] = fmaf(t0, xv[c].y, hxx0[c]);
                            cr0[c] = fmaf(f0.y, t0, cr0[c]);
                            cr0[4 + c] = fmaf(f1.y, t0, cr0[4 + c]);
                            cr0[8 + c] = fmaf(f2.y, t0, cr0[8 + c]);
                        }
                    }
                    {
                        const float w1 = gw[k - 1];
#pragma unroll
                        for (int c = 0; c < GC; c++) {
                            const float t1 = w1 * xv[c].y;
                            hx1[c] += t1;
                            hxx1[c] = fmaf(t1, xv[c].y, hxx1[c]);
                            cr1[c] = fmaf(f0.y, t1, cr1[c]);
                            cr1[4 + c] = fmaf(f1.y, t1, cr1[4 + c]);
                            cr1[8 + c] = fmaf(f2.y, t1, cr1[8 + c]);
                        }
                    }
                }
            }
            float4* d0 = reinterpret_cast<float4*>(&HB(r1, j1, 0));
            d0[0] = make_float4(hx0[0], hx0[1], hx0[2], hx0[3]);
            d0[1] = make_float4(hxx0[0], hxx0[1], hxx0[2], hxx0[3]);
            d0[2] = make_float4(cr0[0], cr0[1], cr0[2], cr0[3]);
            d0[3] = make_float4(cr0[4], cr0[5], cr0[6], cr0[7]);
            d0[4] = make_float4(cr0[8], cr0[9], cr0[10], cr0[11]);
            float4* d1 = reinterpret_cast<float4*>(&HB(r1, j1 + 1, 0));
            d1[0] = make_float4(hx1[0], hx1[1], hx1[2], hx1[3]);
            d1[1] = make_float4(hxx1[0], hxx1[1], hxx1[2], hxx1[3]);
            d1[2] = make_float4(cr1[0], cr1[1], cr1[2], cr1[3]);
            d1[3] = make_float4(cr1[4], cr1[5], cr1[6], cr1[7]);
            d1[4] = make_float4(cr1[8], cr1[9], cr1[10], cr1[11]);
        }
        __syncthreads();

        // phase2: vertical pass with register accumulators + ssim
        float acc[4][5];
#pragma unroll
        for (int li = 0; li < 4; li++)
#pragma unroll
            for (int s = 0; s < 5; s++) acc[li][s] = 0.f;

        const int rbase = slot * 4;
#pragma unroll
        for (int rr = 0; rr < 14; rr++) {
            int r = rbase + rr;
            float v0 = HB(r, pxq, 0 * 4 + c_l);
            float v1 = HB(r, pxq, 1 * 4 + c_l);
            float v2 = HB(r, pxq, 2 * 4 + c_l);
            float v3 = HB(r, pxq, 3 * 4 + c_l);
            float v4 = HB(r, pxq, 4 * 4 + c_l);
#pragma unroll
            for (int li = 0; li < 4; li++) {
                int kk = rr - li;
                if (kk >= 0 && kk < WINN) {
                    float vi = gw[kk];
                    acc[li][0] = fmaf(vi, v0, acc[li][0]);
                    acc[li][1] = fmaf(vi, v1, acc[li][1]);
                    acc[li][2] = fmaf(vi, v2, acc[li][2]);
                    acc[li][3] = fmaf(vi, v3, acc[li][3]);
                    acc[li][4] = fmaf(vi, v4, acc[li][4]);
                }
            }
        }

        float sacc[3] = {0.f, 0.f, 0.f};
#pragma unroll
        for (int li = 0; li < 4; li++) {
            int py = rbase + li;
            if (vx && (oy + py) < HP) {
                float mu2 = acc[li][0];
                float s2 = acc[li][1] - mu2 * mu2;
#pragma unroll
                for (int a = 0; a < 3; a++) {
                    float mu1 = SFS(py, pxq, a);
                    float s1 = SFS(py, pxq, 3 + a) - mu1 * mu1;
                    float s12 = acc[li][2 + a] - mu1 * mu2;
                    float num = (2.f * mu1 * mu2 + C1V) * (2.f * s12 + C2V);
                    float den = (mu1 * mu1 + mu2 * mu2 + C1V) * (s1 + s2 + C2V);
                    sacc[a] += __fdividef(num, den);
                }
            }
        }
#pragma unroll
        for (int a = 0; a < 3; a++) {
            float v = sacc[a];
            v += __shfl_xor_sync(0xffffffffu, v, 4);
            v += __shfl_xor_sync(0xffffffffu, v, 8);
            v += __shfl_xor_sync(0xffffffffu, v, 16);
            if ((tid & 31) < 4) atomicAdd(&s_acc[a * 64 + c0 + c_l], v);
        }
        CP_WAIT;          // next group's tile arrived (this thread's copies)
        __syncthreads();  // visible to all; hb free for overwrite
    }

    if (tid < 192)
        g_part[((size_t)b * NT2 + (ty * 16 + tx)) * 192 + tid] = s_acc[tid];
}

// ---------------------------------------------------------------------------
// Kernel D: reduce tiles -> ssim_info; conv over C; MLP head
// 8-way unrolled independent accumulators for MLP in the tile reduction
// ---------------------------------------------------------------------------
__global__ void kD(const float* __restrict__ conv_w, const float* __restrict__ w1,
                   const float* __restrict__ b1, const float* __restrict__ w2,
                   const float* __restrict__ b2, float* __restrict__ out) {
    int b = blockIdx.x, t = threadIdx.x;
    __shared__ float ss[192];
    __shared__ float h0[64], h1[64];
    float acc[8];
#pragma unroll
    for (int i = 0; i < 8; i++) acc[i] = 0.f;
    for (int k = 0; k < NT2; k += 8) {
#pragma unroll
        for (int i = 0; i < 8; i++)
            acc[i] += g_part[((size_t)b * NT2 + k + i) * 192 + t];
    }
    float sum = ((acc[0] + acc[1]) + (acc[2] + acc[3])) + ((acc[4] + acc[5]) + (acc[6] + acc[7]));
    float si = sum * (1.0f / (246.0f * 246.0f));
    ss[t] = si;
    out[512 + b * 192 + t] = si;  // ssim_info after h
    __syncthreads();
    if (t < 64) {
        float acc2 = 0.f;
#pragma unroll
        for (int a = 0; a < 3; a++)
#pragma unroll
            for (int kh = 0; kh < 3; kh++) {
                int cc = t + kh - 1;
                if (cc >= 0 && cc < 64) acc2 = fmaf(ss[a * 64 + cc], conv_w[a * 3 + kh], acc2);
            }
        h0[t] = fmaxf(acc2, 0.f);
    }
    __syncthreads();
    if (t < 64) {
        float acc2 = b1[t];
#pragma unroll 8
        for (int k = 0; k < 64; k++) acc2 = fmaf(h0[k], w1[t * 64 + k], acc2);
        h1[t] = fmaxf(acc2, 0.f);
    }
    __syncthreads();
    if (t < 64) {
        float acc2 = b2[t];
#pragma unroll 8
        for (int k = 0; k < 64; k++) acc2 = fmaf(h1[k], w2[t * 64 + k], acc2);
        out[b * 64 + t] = __fdividef(1.f, 1.f + __expf(-acc2));
    }
}

// ---------------------------------------------------------------------------
extern "C" void kernel_launch(void* const* d_in, const int* in_sizes, int n_in,
                              void* d_out, int out_size) {
    const float* x = (const float*)d_in[0];
    const int* mask = (const int*)d_in[1];
    const float* conv_w = (const float*)d_in[2];
    const float* w1 = (const float*)d_in[3];
    const float* b1 = (const float*)d_in[4];
    const float* w2 = (const float*)d_in[5];
    const float* b2 = (const float*)d_in[6];
    float* out = (float*)d_out;

    cudaFuncSetAttribute(kC, cudaFuncAttributeMaxDynamicSharedMemorySize, SMEM_TOT);

    kA<<<dim3(HN / 4, BN), 256>>>(x, mask);
    kA2<<<BN, 256>>>();
    kC<<<dim3(16, 16, BN), 256, SMEM_TOT>>>(x, mask);
    kD<<<BN, 192>>>(conv_w, w1, b1, w2, b2, out);
}

// round 16
// speedup vs baseline: 1.0391x; 1.0008x over previous
#include <cuda_runtime.h>
#include <math.h>

#define BN 8
#define CN 64
#define HN 256
#define WN 256
#define WINN 11
#define HP 246
#define TILE 16
#define TIN 26
#define NT2 256
#define GC 4
#define NGRP 16
#define HBS 20
#define XST 48

#define C1V 0.01f
#define C2V 0.09f

__device__ float d_gw[WINN];
__device__ float g_xc[BN * 3 * HN * WN];
__device__ float g_rowstats[BN * HN * 8];
__device__ float g_mean[BN * 3];
__device__ float g_rstd[BN * 3];
__device__ float g_part[BN * 192 * NT2];

__device__ __forceinline__ void cpa4(float* dst, const float* src) {
    unsigned s = (unsigned)__cvta_generic_to_shared(dst);
    asm volatile("cp.async.ca.shared.global [%0],[%1],4;" ::"r"(s), "l"(src));
}
__device__ __forceinline__ void cpa8(float* dst, const float* src) {
    unsigned s = (unsigned)__cvta_generic_to_shared(dst);
    asm volatile("cp.async.ca.shared.global [%0],[%1],8;" ::"r"(s), "l"(src));
}
#define CP_COMMIT asm volatile("cp.async.commit_group;")
#define CP_WAIT asm volatile("cp.async.wait_all;")

// ---------------------------------------------------------------------------
// Kernel A: per-pixel channel max/mean/min -> g_xc, per-row masked sums
// float4 vectorized; grid (HN/4, BN), block 256 = 64 float4-cols x 4 rows
// ---------------------------------------------------------------------------
__global__ void kA(const float* __restrict__ x, const int* __restrict__ mask) {
    const int b = blockIdx.y;
    const int tid = threadIdx.x;
    const int w4 = tid & 63;
    const int r = tid >> 6;
    const int h = blockIdx.x * 4 + r;

    const float4* xp = reinterpret_cast<const float4*>(x + (((size_t)b * CN) * HN + h) * WN) + w4;
    float4 mx = make_float4(-1e30f, -1e30f, -1e30f, -1e30f);
    float4 mn = make_float4(1e30f, 1e30f, 1e30f, 1e30f);
    float4 sm = make_float4(0.f, 0.f, 0.f, 0.f);
#pragma unroll 8
    for (int c = 0; c < CN; c++) {
        float4 v = xp[c * (HN * WN / 4)];
        mx.x = fmaxf(mx.x, v.x); mx.y = fmaxf(mx.y, v.y);
        mx.z = fmaxf(mx.z, v.z); mx.w = fmaxf(mx.w, v.w);
        mn.x = fminf(mn.x, v.x); mn.y = fminf(mn.y, v.y);
        mn.z = fminf(mn.z, v.z); mn.w = fminf(mn.w, v.w);
        sm.x += v.x; sm.y += v.y; sm.z += v.z; sm.w += v.w;
    }
    float4 me = make_float4(sm.x * (1.f / 64.f), sm.y * (1.f / 64.f),
                            sm.z * (1.f / 64.f), sm.w * (1.f / 64.f));
    {
        size_t base = (((size_t)b * 3) * HN + h) * WN + w4 * 4;
        *reinterpret_cast<float4*>(g_xc + base) = mx;
        *reinterpret_cast<float4*>(g_xc + base + (size_t)HN * WN) = me;
        *reinterpret_cast<float4*>(g_xc + base + 2 * (size_t)HN * WN) = mn;
    }

    int4 mi = *reinterpret_cast<const int4*>(mask + ((size_t)b * HN + h) * WN + w4 * 4);
    float m0 = (float)mi.x, m1 = (float)mi.y, m2 = (float)mi.z, m3 = (float)mi.w;
    float vals[7];
    vals[0] = m0 + m1 + m2 + m3;
    vals[1] = mx.x * m0 + mx.y * m1 + mx.z * m2 + mx.w * m3;
    vals[2] = me.x * m0 + me.y * m1 + me.z * m2 + me.w * m3;
    vals[3] = mn.x * m0 + mn.y * m1 + mn.z * m2 + mn.w * m3;
    vals[4] = mx.x * mx.x * m0 + mx.y * mx.y * m1 + mx.z * mx.z * m2 + mx.w * mx.w * m3;
    vals[5] = me.x * me.x * m0 + me.y * me.y * m1 + me.z * me.z * m2 + me.w * me.w * m3;
    vals[6] = mn.x * mn.x * m0 + mn.y * mn.y * m1 + mn.z * mn.z * m2 + mn.w * mn.w * m3;

    __shared__ float red[8][7];
    int lane = tid & 31, wid = tid >> 5;  // warps 2r, 2r+1 belong to row r
#pragma unroll
    for (int i = 0; i < 7; i++) {
        float v = vals[i];
#pragma unroll
        for (int o = 16; o; o >>= 1) v += __shfl_xor_sync(0xffffffffu, v, o);
        if (lane == 0) red[wid][i] = v;
    }
    __syncthreads();
    if (tid < 28) {
        int rr = tid / 7, i = tid - rr * 7;
        g_rowstats[((size_t)b * HN + blockIdx.x * 4 + rr) * 8 + i] =
            red[2 * rr][i] + red[2 * rr + 1][i];
    }
}

// ---------------------------------------------------------------------------
// Kernel A2: reduce row stats -> mean, rstd (fp64); also computes d_gw
// ---------------------------------------------------------------------------
__global__ void kA2() {
    int b = blockIdx.x, t = threadIdx.x;
    if (t == 0) {
        double g[WINN];
        double s = 0.0;
        for (int i = 0; i < WINN; i++) {
            double d = (double)(i - WINN / 2);
            g[i] = exp(-d * d / (2.0 * 1.5 * 1.5));
            s += g[i];
        }
        for (int i = 0; i < WINN; i++) d_gw[i] = (float)(g[i] / s);
    }
    __shared__ double sred[8][7];
    double v[7];
#pragma unroll
    for (int i = 0; i < 7; i++) v[i] = (double)g_rowstats[((size_t)b * HN + t) * 8 + i];
    int lane = t & 31, wid = t >> 5;
#pragma unroll
    for (int i = 0; i < 7; i++) {
        double d = v[i];
#pragma unroll
        for (int o = 16; o; o >>= 1) d += __shfl_xor_sync(0xffffffffu, d, o);
        if (lane == 0) sred[wid][i] = d;
    }
    __syncthreads();
    if (t == 0) {
        double s[7];
#pragma unroll
        for (int i = 0; i < 7; i++) {
            double a = 0.0;
            for (int k = 0; k < 8; k++) a += sred[k][i];
            s[i] = a;
        }
        double n = s[0];
        for (int a = 0; a < 3; a++) {
            double mean = s[1 + a] / n;
            double var = (s[4 + a] - n * mean * mean) / (n - 1.0);
            g_mean[b * 3 + a] = (float)mean;
            g_rstd[b * 3 + a] = (float)(1.0 / sqrt(var));
        }
    }
}

// ---------------------------------------------------------------------------
// Kernel C: fused separable-blur SSIM. Phase-1 j-pair + LDS.64 (stride 48),
// all-thread cpa8 prefetch (R8 scheme), hb stride 20 (conflict-free scalar
// phase 2), fast division. grid (16,16,BN), block 256, 2 CTAs/SM.
// g_part written transposed: [b][stat][tile] for coalesced kD reduction.
// ---------------------------------------------------------------------------
#define XF(a, r, cc) xf_s[((a) * TIN + (r)) * XST + (cc)]
#define HB(r, j, sc) hb[((r) * TILE + (j)) * HBS + (sc)]
#define HFB(r, j, q) hfb[((r) * TILE + (j)) * 6 + (q)]
#define SFS(py, px, q) SfS[((py) * TILE + (px)) * 6 + (q)]

#define XFN (3 * TIN * XST)
#define XSBUF (GC * TIN * XST)
#define SMEM_TOT ((XFN + 2 * XSBUF + TIN * TILE * HBS + TILE * TILE * 6 + 192) * 4)

__device__ __forceinline__ void prefetch_group(const float* __restrict__ xb, float* __restrict__ buf,
                                               int c0, int ox, int oy, int tid, bool interior) {
    if (interior) {
        for (int idx = tid; idx < GC * TIN * 13; idx += 256) {
            int c = idx / (TIN * 13);
            int rem = idx - c * (TIN * 13);
            int rr = rem / 13, q = rem - rr * 13;
            cpa8(buf + (c * TIN + rr) * XST + 2 * q,
                 xb + (((size_t)(c0 + c)) * HN + (oy + rr)) * WN + ox + 2 * q);
        }
    } else {
        for (int idx = tid; idx < GC * TIN * TIN; idx += 256) {
            int c = idx / (TIN * TIN);
            int rem = idx - c * (TIN * TIN);
            int rr = rem / TIN, cc = rem - rr * TIN;
            int gy = min(oy + rr, HN - 1), gx = min(ox + cc, WN - 1);
            cpa4(buf + (c * TIN + rr) * XST + cc,
                 xb + (((size_t)(c0 + c)) * HN + gy) * WN + gx);
        }
    }
    CP_COMMIT;
}

__global__ __launch_bounds__(256, 2) void kC(const float* __restrict__ x,
                                             const int* __restrict__ mask) {
    extern __shared__ float smem[];
    float* xf_s = smem;                       // [3][26][48]
    float* xs0 = xf_s + XFN;                  // 2 x [4][26][48]
    float* hb = xs0 + 2 * XSBUF;              // [26][16][20]
    float* SfS = hb + TIN * TILE * HBS;       // [16][16][6]
    float* s_acc = SfS + TILE * TILE * 6;     // [192]
    float* hfb = xs0 + XSBUF;                 // aliases xs buffer 1 (dead before g=1 prefetch)

    const int tx = blockIdx.x, ty = blockIdx.y, b = blockIdx.z;
    const int ox = tx * TILE, oy = ty * TILE;
    const int tid = threadIdx.x;
    const bool interior = (ox + TIN <= WN) && (oy + TIN <= HN);
    const float* xb = x + (size_t)b * CN * HN * WN;

    float gw[WINN];
#pragma unroll
    for (int i = 0; i < WINN; i++) gw[i] = d_gw[i];

    if (tid < 192) s_acc[tid] = 0.f;

    // kick off prefetch of channel group 0 into xs buffer 0
    prefetch_group(xb, xs0, 0, ox, oy, tid, interior);

    // load xf tile: xf = (xc - mean) * rstd * mask
    {
        float mean[3], rstd[3];
#pragma unroll
        for (int a = 0; a < 3; a++) {
            mean[a] = g_mean[b * 3 + a];
            rstd[a] = g_rstd[b * 3 + a];
        }
        for (int idx = tid; idx < 3 * TIN * TIN; idx += 256) {
            int a = idx / (TIN * TIN);
            int rem = idx - a * (TIN * TIN);
            int rr = rem / TIN, cc = rem - rr * TIN;
            int gy = min(oy + rr, HN - 1), gx = min(ox + cc, WN - 1);
            float mc = (float)mask[((size_t)b * HN + gy) * WN + gx];
            float v = g_xc[(((size_t)b * 3 + a) * HN + gy) * WN + gx];
            XF(a, rr, cc) = (v - mean[a]) * rstd[a] * mc;
        }
    }
    __syncthreads();

    // phase0: horizontal conv of xf, xf^2 -> hfb (aliases xs buf 1)
    for (int p = tid; p < TIN * TILE; p += 256) {
        int r = p / TILE, j = p - (p / TILE) * TILE;
        float hf[3] = {0, 0, 0}, hff[3] = {0, 0, 0};
#pragma unroll
        for (int k = 0; k < WINN; k++) {
            float wk = gw[k];
#pragma unroll
            for (int a = 0; a < 3; a++) {
                float v = XF(a, r, j + k);
                float t = wk * v;
                hf[a] += t;
                hff[a] = fmaf(t, v, hff[a]);
            }
        }
#pragma unroll
        for (int a = 0; a < 3; a++) {
            HFB(r, j, a) = hf[a];
            HFB(r, j, 3 + a) = hff[a];
        }
    }
    __syncthreads();

    // phase0b: vertical -> Sf, Sff per output pixel
    {
        int px = tid & 15, py = tid >> 4;
        float s[6] = {0, 0, 0, 0, 0, 0};
#pragma unroll
        for (int i = 0; i < WINN; i++) {
            float vi = gw[i];
#pragma unroll
            for (int q = 0; q < 6; q++) s[q] = fmaf(vi, HFB(py + i, px, q), s[q]);
        }
#pragma unroll
        for (int q = 0; q < 6; q++) SFS(py, px, q) = s[q];
    }
    CP_WAIT;
    __syncthreads();  // group-0 tile + SfS visible; hfb dead -> buf1 reusable

    const int c_l = tid & 3;
    const int pxq = (tid >> 2) & 15;
    const int slot = tid >> 6;
    const bool vx = (ox + pxq) < HP;

    // phase-1 item: (r, jp) with j = 2*jp; 208 items on tids 0..207
    const int r1 = tid >> 3;
    const int j1 = (tid & 7) * 2;

    for (int g = 0; g < NGRP; g++) {
        float* xs = xs0 + (g & 1) * XSBUF;
        if (g + 1 < NGRP)
            prefetch_group(xb, xs0 + ((g + 1) & 1) * XSBUF, (g + 1) * GC, ox, oy, tid, interior);
        int c0 = g * GC;

        // phase1: horizontal pass, j-pair register blocking, float2 loads -> hb
        if (tid < 208) {
            const float* xfr = xf_s + r1 * XST + j1;
            const float* xsr = xs + r1 * XST + j1;
            float hx0[4] = {0, 0, 0, 0}, hx1[4] = {0, 0, 0, 0};
            float hxx0[4] = {0, 0, 0, 0}, hxx1[4] = {0, 0, 0, 0};
            float cr0[12], cr1[12];
#pragma unroll
            for (int q = 0; q < 12; q++) {
                cr0[q] = 0.f;
                cr1[q] = 0.f;
            }
#pragma unroll
            for (int kk = 0; kk < 6; kk++) {
                const float2 f0 = *reinterpret_cast<const float2*>(xfr + 2 * kk);
                const float2 f1 = *reinterpret_cast<const float2*>(xfr + TIN * XST + 2 * kk);
                const float2 f2 = *reinterpret_cast<const float2*>(xfr + 2 * TIN * XST + 2 * kk);
                float2 xv[GC];
#pragma unroll
                for (int c = 0; c < GC; c++)
                    xv[c] = *reinterpret_cast<const float2*>(xsr + c * TIN * XST + 2 * kk);
                {
                    const int k = 2 * kk;
                    const float w0 = gw[k];
#pragma unroll
                    for (int c = 0; c < GC; c++) {
                        const float t0 = w0 * xv[c].x;
                        hx0[c] += t0;
                        hxx0[c] = fmaf(t0, xv[c].x, hxx0[c]);
                        cr0[c] = fmaf(f0.x, t0, cr0[c]);
                        cr0[4 + c] = fmaf(f1.x, t0, cr0[4 + c]);
                        cr0[8 + c] = fmaf(f2.x, t0, cr0[8 + c]);
                    }
                    if (k > 0) {
                        const float w1 = gw[k - 1];
#pragma unroll
                        for (int c = 0; c < GC; c++) {
                            const float t1 = w1 * xv[c].x;
                            hx1[c] += t1;
                            hxx1[c] = fmaf(t1, xv[c].x, hxx1[c]);
                            cr1[c] = fmaf(f0.x, t1, cr1[c]);
                            cr1[4 + c] = fmaf(f1.x, t1, cr1[4 + c]);
                            cr1[8 + c] = fmaf(f2.x, t1, cr1[8 + c]);
                        }
                    }
                }
                {
                    const int k = 2 * kk + 1;
                    if (k < 11) {
                        const float w0 = gw[k];
#pragma unroll
                        for (int c = 0; c < GC; c++) {
                            const float t0 = w0 * xv[c].y;
                            hx0[c] += t0;
                            hxx0[c] = fmaf(t0, xv[c].y, hxx0[c]);
                            cr0[c] = fmaf(f0.y, t0, cr0[c]);
                            cr0[4 + c] = fmaf(f1.y, t0, cr0[4 + c]);
                            cr0[8 + c] = fmaf(f2.y, t0, cr0[8 + c]);
                        }
                    }
                    {
                        const float w1 = gw[k - 1];
#pragma unroll
                        for (int c = 0; c < GC; c++) {
                            const float t1 = w1 * xv[c].y;
                            hx1[c] += t1;
                            hxx1[c] = fmaf(t1, xv[c].y, hxx1[c]);
                            cr1[c] = fmaf(f0.y, t1, cr1[c]);
                            cr1[4 + c] = fmaf(f1.y, t1, cr1[4 + c]);
                            cr1[8 + c] = fmaf(f2.y, t1, cr1[8 + c]);
                        }
                    }
                }
            }
            float4* d0 = reinterpret_cast<float4*>(&HB(r1, j1, 0));
            d0[0] = make_float4(hx0[0], hx0[1], hx0[2], hx0[3]);
            d0[1] = make_float4(hxx0[0], hxx0[1], hxx0[2], hxx0[3]);
            d0[2] = make_float4(cr0[0], cr0[1], cr0[2], cr0[3]);
            d0[3] = make_float4(cr0[4], cr0[5], cr0[6], cr0[7]);
            d0[4] = make_float4(cr0[8], cr0[9], cr0[10], cr0[11]);
            float4* d1 = reinterpret_cast<float4*>(&HB(r1, j1 + 1, 0));
            d1[0] = make_float4(hx1[0], hx1[1], hx1[2], hx1[3]);
            d1[1] = make_float4(hxx1[0], hxx1[1], hxx1[2], hxx1[3]);
            d1[2] = make_float4(cr1[0], cr1[1], cr1[2], cr1[3]);
            d1[3] = make_float4(cr1[4], cr1[5], cr1[6], cr1[7]);
            d1[4] = make_float4(cr1[8], cr1[9], cr1[10], cr1[11]);
        }
        __syncthreads();

        // phase2: vertical pass with register accumulators + ssim
        float acc[4][5];
#pragma unroll
        for (int li = 0; li < 4; li++)
#pragma unroll
            for (int s = 0; s < 5; s++) acc[li][s] = 0.f;

        const int rbase = slot * 4;
#pragma unroll
        for (int rr = 0; rr < 14; rr++) {
            int r = rbase + rr;
            float v0 = HB(r, pxq, 0 * 4 + c_l);
            float v1 = HB(r, pxq, 1 * 4 + c_l);
            float v2 = HB(r, pxq, 2 * 4 + c_l);
            float v3 = HB(r, pxq, 3 * 4 + c_l);
            float v4 = HB(r, pxq, 4 * 4 + c_l);
#pragma unroll
            for (int li = 0; li < 4; li++) {
                int kk = rr - li;
                if (kk >= 0 && kk < WINN) {
                    float vi = gw[kk];
                    acc[li][0] = fmaf(vi, v0, acc[li][0]);
                    acc[li][1] = fmaf(vi, v1, acc[li][1]);
                    acc[li][2] = fmaf(vi, v2, acc[li][2]);
                    acc[li][3] = fmaf(vi, v3, acc[li][3]);
                    acc[li][4] = fmaf(vi, v4, acc[li][4]);
                }
            }
        }

        float sacc[3] = {0.f, 0.f, 0.f};
#pragma unroll
        for (int li = 0; li < 4; li++) {
            int py = rbase + li;
            if (vx && (oy + py) < HP) {
                float mu2 = acc[li][0];
                float s2 = acc[li][1] - mu2 * mu2;
#pragma unroll
                for (int a = 0; a < 3; a++) {
                    float mu1 = SFS(py, pxq, a);
                    float s1 = SFS(py, pxq, 3 + a) - mu1 * mu1;
                    float s12 = acc[li][2 + a] - mu1 * mu2;
                    float num = (2.f * mu1 * mu2 + C1V) * (2.f * s12 + C2V);
                    float den = (mu1 * mu1 + mu2 * mu2 + C1V) * (s1 + s2 + C2V);
                    sacc[a] += __fdividef(num, den);
                }
            }
        }
#pragma unroll
        for (int a = 0; a < 3; a++) {
            float v = sacc[a];
            v += __shfl_xor_sync(0xffffffffu, v, 4);
            v += __shfl_xor_sync(0xffffffffu, v, 8);
            v += __shfl_xor_sync(0xffffffffu, v, 16);
            if ((tid & 31) < 4) atomicAdd(&s_acc[a * 64 + c0 + c_l], v);
        }
        CP_WAIT;          // next group's tile arrived (this thread's copies)
        __syncthreads();  // visible to all; hb free for overwrite
    }

    if (tid < 192)
        g_part[((size_t)b * 192 + tid) * NT2 + (ty * 16 + tx)] = s_acc[tid];
}

// ---------------------------------------------------------------------------
// Kernel D: coalesced warp-per-output tile reduction -> ssim_info;
// conv over C; MLP head. grid BN, block 256.
// ---------------------------------------------------------------------------
__global__ void kD(const float* __restrict__ conv_w, const float* __restrict__ w1,
                   const float* __restrict__ b1, const float* __restrict__ w2,
                   const float* __restrict__ b2, float* __restrict__ out) {
    int b = blockIdx.x, t = threadIdx.x;
    __shared__ float ss[192];
    __shared__ float h0[64], h1[64];
    int w = t >> 5, lane = t & 31;
    for (int o = w; o < 192; o += 8) {
        const float* p = g_part + ((size_t)b * 192 + o) * NT2;
        float v = 0.f;
#pragma unroll
        for (int i = 0; i < 8; i++) v += p[lane + 32 * i];
#pragma unroll
        for (int off = 16; off; off >>= 1) v += __shfl_xor_sync(0xffffffffu, v, off);
        if (lane == 0) {
            float si = v * (1.0f / (246.0f * 246.0f));
            ss[o] = si;
            out[512 + b * 192 + o] = si;  // ssim_info after h
        }
    }
    __syncthreads();
    if (t < 64) {
        float acc = 0.f;
#pragma unroll
        for (int a = 0; a < 3; a++)
#pragma unroll
            for (int kh = 0; kh < 3; kh++) {
                int cc = t + kh - 1;
                if (cc >= 0 && cc < 64) acc = fmaf(ss[a * 64 + cc], conv_w[a * 3 + kh], acc);
            }
        h0[t] = fmaxf(acc, 0.f);
    }
    __syncthreads();
    if (t < 64) {
        float acc = b1[t];
#pragma unroll 8
        for (int k = 0; k < 64; k++) acc = fmaf(h0[k], w1[t * 64 + k], acc);
        h1[t] = fmaxf(acc, 0.f);
    }
    __syncthreads();
    if (t < 64) {
        float acc = b2[t];
#pragma unroll 8
        for (int k = 0; k < 64; k++) acc = fmaf(h1[k], w2[t * 64 + k], acc);
        out[b * 64 + t] = __fdividef(1.f, 1.f + __expf(-acc));
    }
}

// ---------------------------------------------------------------------------
extern "C" void kernel_launch(void* const* d_in, const int* in_sizes, int n_in,
                              void* d_out, int out_size) {
    const float* x = (const float*)d_in[0];
    const int* mask = (const int*)d_in[1];
    const float* conv_w = (const float*)d_in[2];
    const float* w1 = (const float*)d_in[3];
    const float* b1 = (const float*)d_in[4];
    const float* w2 = (const float*)d_in[5];
    const float* b2 = (const float*)d_in[6];
    float* out = (float*)d_out;

    cudaFuncSetAttribute(kC, cudaFuncAttributeMaxDynamicSharedMemorySize, SMEM_TOT);

    kA<<<dim3(HN / 4, BN), 256>>>(x, mask);
    kA2<<<BN, 256>>>();
    kC<<<dim3(16, 16, BN), 256, SMEM_TOT>>>(x, mask);
    kD<<<BN, 256>>>(conv_w, w1, b1, w2, b2, out);
}

// round 17
// speedup vs baseline: 1.0587x; 1.0189x over previous
#include <cuda_runtime.h>
#include <math.h>

#define BN 8
#define CN 64
#define HN 256
#define WN 256
#define WINN 11
#define HP 246
#define TILE 16
#define TIN 26
#define NT2 256
#define GC 4
#define NGRP 16
#define HBS 20
#define XST 48

#define C1V 0.01f
#define C2V 0.09f

__device__ float d_gw[WINN];
__device__ float g_xc[BN * 3 * HN * WN];
__device__ float g_rowstats[BN * HN * 8];
__device__ float g_mean[BN * 3];
__device__ float g_rstd[BN * 3];
__device__ float g_part[BN * 192 * NT2];

__device__ __forceinline__ void cpa4(float* dst, const float* src) {
    unsigned s = (unsigned)__cvta_generic_to_shared(dst);
    asm volatile("cp.async.ca.shared.global [%0],[%1],4;" ::"r"(s), "l"(src));
}
__device__ __forceinline__ void cpa8(float* dst, const float* src) {
    unsigned s = (unsigned)__cvta_generic_to_shared(dst);
    asm volatile("cp.async.ca.shared.global [%0],[%1],8;" ::"r"(s), "l"(src));
}
#define CP_COMMIT asm volatile("cp.async.commit_group;")
#define CP_WAIT asm volatile("cp.async.wait_all;")

// ---------------------------------------------------------------------------
// Kernel A: per-pixel channel max/mean/min -> g_xc, per-row masked sums
// float4 vectorized; grid (HN/4, BN), block 256 = 64 float4-cols x 4 rows
// ---------------------------------------------------------------------------
__global__ void kA(const float* __restrict__ x, const int* __restrict__ mask) {
    const int b = blockIdx.y;
    const int tid = threadIdx.x;
    const int w4 = tid & 63;
    const int r = tid >> 6;
    const int h = blockIdx.x * 4 + r;

    const float4* xp = reinterpret_cast<const float4*>(x + (((size_t)b * CN) * HN + h) * WN) + w4;
    float4 mx = make_float4(-1e30f, -1e30f, -1e30f, -1e30f);
    float4 mn = make_float4(1e30f, 1e30f, 1e30f, 1e30f);
    float4 sm = make_float4(0.f, 0.f, 0.f, 0.f);
#pragma unroll 8
    for (int c = 0; c < CN; c++) {
        float4 v = xp[c * (HN * WN / 4)];
        mx.x = fmaxf(mx.x, v.x); mx.y = fmaxf(mx.y, v.y);
        mx.z = fmaxf(mx.z, v.z); mx.w = fmaxf(mx.w, v.w);
        mn.x = fminf(mn.x, v.x); mn.y = fminf(mn.y, v.y);
        mn.z = fminf(mn.z, v.z); mn.w = fminf(mn.w, v.w);
        sm.x += v.x; sm.y += v.y; sm.z += v.z; sm.w += v.w;
    }
    float4 me = make_float4(sm.x * (1.f / 64.f), sm.y * (1.f / 64.f),
                            sm.z * (1.f / 64.f), sm.w * (1.f / 64.f));
    {
        size_t base = (((size_t)b * 3) * HN + h) * WN + w4 * 4;
        *reinterpret_cast<float4*>(g_xc + base) = mx;
        *reinterpret_cast<float4*>(g_xc + base + (size_t)HN * WN) = me;
        *reinterpret_cast<float4*>(g_xc + base + 2 * (size_t)HN * WN) = mn;
    }

    int4 mi = *reinterpret_cast<const int4*>(mask + ((size_t)b * HN + h) * WN + w4 * 4);
    float m0 = (float)mi.x, m1 = (float)mi.y, m2 = (float)mi.z, m3 = (float)mi.w;
    float vals[7];
    vals[0] = m0 + m1 + m2 + m3;
    vals[1] = mx.x * m0 + mx.y * m1 + mx.z * m2 + mx.w * m3;
    vals[2] = me.x * m0 + me.y * m1 + me.z * m2 + me.w * m3;
    vals[3] = mn.x * m0 + mn.y * m1 + mn.z * m2 + mn.w * m3;
    vals[4] = mx.x * mx.x * m0 + mx.y * mx.y * m1 + mx.z * mx.z * m2 + mx.w * mx.w * m3;
    vals[5] = me.x * me.x * m0 + me.y * me.y * m1 + me.z * me.z * m2 + me.w * me.w * m3;
    vals[6] = mn.x * mn.x * m0 + mn.y * mn.y * m1 + mn.z * mn.z * m2 + mn.w * mn.w * m3;

    __shared__ float red[8][7];
    int lane = tid & 31, wid = tid >> 5;  // warps 2r, 2r+1 belong to row r
#pragma unroll
    for (int i = 0; i < 7; i++) {
        float v = vals[i];
#pragma unroll
        for (int o = 16; o; o >>= 1) v += __shfl_xor_sync(0xffffffffu, v, o);
        if (lane == 0) red[wid][i] = v;
    }
    __syncthreads();
    if (tid < 28) {
        int rr = tid / 7, i = tid - rr * 7;
        g_rowstats[((size_t)b * HN + blockIdx.x * 4 + rr) * 8 + i] =
            red[2 * rr][i] + red[2 * rr + 1][i];
    }
}

// ---------------------------------------------------------------------------
// Kernel A2: reduce row stats -> mean, rstd (fp64); also computes d_gw
// ---------------------------------------------------------------------------
__global__ void kA2() {
    int b = blockIdx.x, t = threadIdx.x;
    if (t == 0) {
        double g[WINN];
        double s = 0.0;
        for (int i = 0; i < WINN; i++) {
            double d = (double)(i - WINN / 2);
            g[i] = exp(-d * d / (2.0 * 1.5 * 1.5));
            s += g[i];
        }
        for (int i = 0; i < WINN; i++) d_gw[i] = (float)(g[i] / s);
    }
    __shared__ double sred[8][7];
    double v[7];
#pragma unroll
    for (int i = 0; i < 7; i++) v[i] = (double)g_rowstats[((size_t)b * HN + t) * 8 + i];
    int lane = t & 31, wid = t >> 5;
#pragma unroll
    for (int i = 0; i < 7; i++) {
        double d = v[i];
#pragma unroll
        for (int o = 16; o; o >>= 1) d += __shfl_xor_sync(0xffffffffu, d, o);
        if (lane == 0) sred[wid][i] = d;
    }
    __syncthreads();
    if (t == 0) {
        double s[7];
#pragma unroll
        for (int i = 0; i < 7; i++) {
            double a = 0.0;
            for (int k = 0; k < 8; k++) a += sred[k][i];
            s[i] = a;
        }
        double n = s[0];
        for (int a = 0; a < 3; a++) {
            double mean = s[1 + a] / n;
            double var = (s[4 + a] - n * mean * mean) / (n - 1.0);
            g_mean[b * 3 + a] = (float)mean;
            g_rstd[b * 3 + a] = (float)(1.0 / sqrt(var));
        }
    }
}

// ---------------------------------------------------------------------------
// Kernel C: fused separable-blur SSIM. Phase-1 j-pair + LDS.64 (stride 48),
// all-thread cpa8 prefetch (R8 scheme), hb stride 20 (conflict-free scalar
// phase 2), fast division. grid (16,16,BN), block 256, 2 CTAs/SM.
// g_part written transposed: [b][stat][tile] for coalesced kD reduction.
// ---------------------------------------------------------------------------
#define XF(a, r, cc) xf_s[((a) * TIN + (r)) * XST + (cc)]
#define HB(r, j, sc) hb[((r) * TILE + (j)) * HBS + (sc)]
#define HFB(r, j, q) hfb[((r) * TILE + (j)) * 6 + (q)]
#define SFS(py, px, q) SfS[((py) * TILE + (px)) * 6 + (q)]

#define XFN (3 * TIN * XST)
#define XSBUF (GC * TIN * XST)
#define SMEM_TOT ((XFN + 2 * XSBUF + TIN * TILE * HBS + TILE * TILE * 6 + 192) * 4)

__device__ __forceinline__ void prefetch_group(const float* __restrict__ xb, float* __restrict__ buf,
                                               int c0, int ox, int oy, int tid, bool interior) {
    if (interior) {
        for (int idx = tid; idx < GC * TIN * 13; idx += 256) {
            int c = idx / (TIN * 13);
            int rem = idx - c * (TIN * 13);
            int rr = rem / 13, q = rem - rr * 13;
            cpa8(buf + (c * TIN + rr) * XST + 2 * q,
                 xb + (((size_t)(c0 + c)) * HN + (oy + rr)) * WN + ox + 2 * q);
        }
    } else {
        for (int idx = tid; idx < GC * TIN * TIN; idx += 256) {
            int c = idx / (TIN * TIN);
            int rem = idx - c * (TIN * TIN);
            int rr = rem / TIN, cc = rem - rr * TIN;
            int gy = min(oy + rr, HN - 1), gx = min(ox + cc, WN - 1);
            cpa4(buf + (c * TIN + rr) * XST + cc,
                 xb + (((size_t)(c0 + c)) * HN + gy) * WN + gx);
        }
    }
    CP_COMMIT;
}

__global__ __launch_bounds__(256, 2) void kC(const float* __restrict__ x,
                                             const int* __restrict__ mask) {
    extern __shared__ float smem[];
    float* xf_s = smem;                       // [3][26][48]
    float* xs0 = xf_s + XFN;                  // 2 x [4][26][48]
    float* hb = xs0 + 2 * XSBUF;              // [26][16][20]
    float* SfS = hb + TIN * TILE * HBS;       // [16][16][6]
    float* s_acc = SfS + TILE * TILE * 6;     // [192]
    float* hfb = xs0 + XSBUF;                 // aliases xs buffer 1 (dead before g=1 prefetch)

    const int tx = blockIdx.x, ty = blockIdx.y, b = blockIdx.z;
    const int ox = tx * TILE, oy = ty * TILE;
    const int tid = threadIdx.x;
    const bool interior = (ox + TIN <= WN) && (oy + TIN <= HN);
    const float* xb = x + (size_t)b * CN * HN * WN;

    float gw[WINN];
#pragma unroll
    for (int i = 0; i < WINN; i++) gw[i] = d_gw[i];

    if (tid < 192) s_acc[tid] = 0.f;

    // kick off prefetch of channel group 0 into xs buffer 0
    prefetch_group(xb, xs0, 0, ox, oy, tid, interior);

    // load xf tile: xf = (xc - mean) * rstd * mask
    {
        float mean[3], rstd[3];
#pragma unroll
        for (int a = 0; a < 3; a++) {
            mean[a] = g_mean[b * 3 + a];
            rstd[a] = g_rstd[b * 3 + a];
        }
        for (int idx = tid; idx < 3 * TIN * TIN; idx += 256) {
            int a = idx / (TIN * TIN);
            int rem = idx - a * (TIN * TIN);
            int rr = rem / TIN, cc = rem - rr * TIN;
            int gy = min(oy + rr, HN - 1), gx = min(ox + cc, WN - 1);
            float mc = (float)mask[((size_t)b * HN + gy) * WN + gx];
            float v = g_xc[(((size_t)b * 3 + a) * HN + gy) * WN + gx];
            XF(a, rr, cc) = (v - mean[a]) * rstd[a] * mc;
        }
    }
    __syncthreads();

    // phase0: horizontal conv of xf, xf^2 -> hfb (aliases xs buf 1)
    for (int p = tid; p < TIN * TILE; p += 256) {
        int r = p / TILE, j = p - (p / TILE) * TILE;
        float hf[3] = {0, 0, 0}, hff[3] = {0, 0, 0};
#pragma unroll
        for (int k = 0; k < WINN; k++) {
            float wk = gw[k];
#pragma unroll
            for (int a = 0; a < 3; a++) {
                float v = XF(a, r, j + k);
                float t = wk * v;
                hf[a] += t;
                hff[a] = fmaf(t, v, hff[a]);
            }
        }
#pragma unroll
        for (int a = 0; a < 3; a++) {
            HFB(r, j, a) = hf[a];
            HFB(r, j, 3 + a) = hff[a];
        }
    }
    __syncthreads();

    // phase0b: vertical -> Sf, Sff per output pixel
    {
        int px = tid & 15, py = tid >> 4;
        float s[6] = {0, 0, 0, 0, 0, 0};
#pragma unroll
        for (int i = 0; i < WINN; i++) {
            float vi = gw[i];
#pragma unroll
            for (int q = 0; q < 6; q++) s[q] = fmaf(vi, HFB(py + i, px, q), s[q]);
        }
#pragma unroll
        for (int q = 0; q < 6; q++) SFS(py, px, q) = s[q];
    }
    CP_WAIT;
    __syncthreads();  // group-0 tile + SfS visible; hfb dead -> buf1 reusable

    const int c_l = tid & 3;
    const int pxq = (tid >> 2) & 15;
    const int slot = tid >> 6;
    const bool vx = (ox + pxq) < HP;

    // phase-1 item: (r, jp) with j = 2*jp; 208 items on tids 0..207
    const int r1 = tid >> 3;
    const int j1 = (tid & 7) * 2;

    for (int g = 0; g < NGRP; g++) {
        float* xs = xs0 + (g & 1) * XSBUF;
        if (g + 1 < NGRP)
            prefetch_group(xb, xs0 + ((g + 1) & 1) * XSBUF, (g + 1) * GC, ox, oy, tid, interior);
        int c0 = g * GC;

        // phase1: horizontal pass, j-pair register blocking, float2 loads -> hb
        if (tid < 208) {
            const float* xfr = xf_s + r1 * XST + j1;
            const float* xsr = xs + r1 * XST + j1;
            float hx0[4] = {0, 0, 0, 0}, hx1[4] = {0, 0, 0, 0};
            float hxx0[4] = {0, 0, 0, 0}, hxx1[4] = {0, 0, 0, 0};
            float cr0[12], cr1[12];
#pragma unroll
            for (int q = 0; q < 12; q++) {
                cr0[q] = 0.f;
                cr1[q] = 0.f;
            }
#pragma unroll
            for (int kk = 0; kk < 6; kk++) {
                const float2 f0 = *reinterpret_cast<const float2*>(xfr + 2 * kk);
                const float2 f1 = *reinterpret_cast<const float2*>(xfr + TIN * XST + 2 * kk);
                const float2 f2 = *reinterpret_cast<const float2*>(xfr + 2 * TIN * XST + 2 * kk);
                float2 xv[GC];
#pragma unroll
                for (int c = 0; c < GC; c++)
                    xv[c] = *reinterpret_cast<const float2*>(xsr + c * TIN * XST + 2 * kk);
                {
                    const int k = 2 * kk;
                    const float w0 = gw[k];
#pragma unroll
                    for (int c = 0; c < GC; c++) {
                        const float t0 = w0 * xv[c].x;
                        hx0[c] += t0;
                        hxx0[c] = fmaf(t0, xv[c].x, hxx0[c]);
                        cr0[c] = fmaf(f0.x, t0, cr0[c]);
                        cr0[4 + c] = fmaf(f1.x, t0, cr0[4 + c]);
                        cr0[8 + c] = fmaf(f2.x, t0, cr0[8 + c]);
                    }
                    if (k > 0) {
                        const float w1 = gw[k - 1];
#pragma unroll
                        for (int c = 0; c < GC; c++) {
                            const float t1 = w1 * xv[c].x;
                            hx1[c] += t1;
                            hxx1[c] = fmaf(t1, xv[c].x, hxx1[c]);
                            cr1[c] = fmaf(f0.x, t1, cr1[c]);
                            cr1[4 + c] = fmaf(f1.x, t1, cr1[4 + c]);
                            cr1[8 + c] = fmaf(f2.x, t1, cr1[8 + c]);
                        }
                    }
                }
                {
                    const int k = 2 * kk + 1;
                    if (k < 11) {
                        const float w0 = gw[k];
#pragma unroll
                        for (int c = 0; c < GC; c++) {
                            const float t0 = w0 * xv[c].y;
                            hx0[c] += t0;
                            hxx0[c] = fmaf(t0, xv[c].y, hxx0[c]);
                            cr0[c] = fmaf(f0.y, t0, cr0[c]);
                            cr0[4 + c] = fmaf(f1.y, t0, cr0[4 + c]);
                            cr0[8 + c] = fmaf(f2.y, t0, cr0[8 + c]);
                        }
                    }
                    {
                        const float w1 = gw[k - 1];
#pragma unroll
                        for (int c = 0; c < GC; c++) {
                            const float t1 = w1 * xv[c].y;
                            hx1[c] += t1;
                            hxx1[c] = fmaf(t1, xv[c].y, hxx1[c]);
                            cr1[c] = fmaf(f0.y, t1, cr1[c]);
                            cr1[4 + c] = fmaf(f1.y, t1, cr1[4 + c]);
                            cr1[8 + c] = fmaf(f2.y, t1, cr1[8 + c]);
                        }
                    }
                }
            }
            float4* d0 = reinterpret_cast<float4*>(&HB(r1, j1, 0));
            d0[0] = make_float4(hx0[0], hx0[1], hx0[2], hx0[3]);
            d0[1] = make_float4(hxx0[0], hxx0[1], hxx0[2], hxx0[3]);
            d0[2] = make_float4(cr0[0], cr0[1], cr0[2], cr0[3]);
            d0[3] = make_float4(cr0[4], cr0[5], cr0[6], cr0[7]);
            d0[4] = make_float4(cr0[8], cr0[9], cr0[10], cr0[11]);
            float4* d1 = reinterpret_cast<float4*>(&HB(r1, j1 + 1, 0));
            d1[0] = make_float4(hx1[0], hx1[1], hx1[2], hx1[3]);
            d1[1] = make_float4(hxx1[0], hxx1[1], hxx1[2], hxx1[3]);
            d1[2] = make_float4(cr1[0], cr1[1], cr1[2], cr1[3]);
            d1[3] = make_float4(cr1[4], cr1[5], cr1[6], cr1[7]);
            d1[4] = make_float4(cr1[8], cr1[9], cr1[10], cr1[11]);
        }
        __syncthreads();

        // phase2: vertical pass with register accumulators + ssim
        float acc[4][5];
#pragma unroll
        for (int li = 0; li < 4; li++)
#pragma unroll
            for (int s = 0; s < 5; s++) acc[li][s] = 0.f;

        const int rbase = slot * 4;
#pragma unroll
        for (int rr = 0; rr < 14; rr++) {
            int r = rbase + rr;
            float v0 = HB(r, pxq, 0 * 4 + c_l);
            float v1 = HB(r, pxq, 1 * 4 + c_l);
            float v2 = HB(r, pxq, 2 * 4 + c_l);
            float v3 = HB(r, pxq, 3 * 4 + c_l);
            float v4 = HB(r, pxq, 4 * 4 + c_l);
#pragma unroll
            for (int li = 0; li < 4; li++) {
                int kk = rr - li;
                if (kk >= 0 && kk < WINN) {
                    float vi = gw[kk];
                    acc[li][0] = fmaf(vi, v0, acc[li][0]);
                    acc[li][1] = fmaf(vi, v1, acc[li][1]);
                    acc[li][2] = fmaf(vi, v2, acc[li][2]);
                    acc[li][3] = fmaf(vi, v3, acc[li][3]);
                    acc[li][4] = fmaf(vi, v4, acc[li][4]);
                }
            }
        }

        float sacc[3] = {0.f, 0.f, 0.f};
#pragma unroll
        for (int li = 0; li < 4; li++) {
            int py = rbase + li;
            if (vx && (oy + py) < HP) {
                float mu2 = acc[li][0];
                float s2 = acc[li][1] - mu2 * mu2;
#pragma unroll
                for (int a = 0; a < 3; a++) {
                    float mu1 = SFS(py, pxq, a);
                    float s1 = SFS(py, pxq, 3 + a) - mu1 * mu1;
                    float s12 = acc[li][2 + a] - mu1 * mu2;
                    float num = (2.f * mu1 * mu2 + C1V) * (2.f * s12 + C2V);
                    float den = (mu1 * mu1 + mu2 * mu2 + C1V) * (s1 + s2 + C2V);
                    sacc[a] += __fdividef(num, den);
                }
            }
        }
#pragma unroll
        for (int a = 0; a < 3; a++) {
            float v = sacc[a];
            v += __shfl_xor_sync(0xffffffffu, v, 4);
            v += __shfl_xor_sync(0xffffffffu, v, 8);
            v += __shfl_xor_sync(0xffffffffu, v, 16);
            if ((tid & 31) < 4) atomicAdd(&s_acc[a * 64 + c0 + c_l], v);
        }
        CP_WAIT;          // next group's tile arrived (this thread's copies)
        __syncthreads();  // visible to all; hb free for overwrite
    }

    if (tid < 192)
        g_part[((size_t)b * 192 + tid) * NT2 + (ty * 16 + tx)] = s_acc[tid];
}

// ---------------------------------------------------------------------------
// Kernel D: coalesced warp-per-output tile reduction (32 warps) -> ssim_info;
// conv over C; MLP head. grid BN, block 1024.
// ---------------------------------------------------------------------------
__global__ void kD(const float* __restrict__ conv_w, const float* __restrict__ w1,
                   const float* __restrict__ b1, const float* __restrict__ w2,
                   const float* __restrict__ b2, float* __restrict__ out) {
    int b = blockIdx.x, t = threadIdx.x;
    __shared__ float ss[192];
    __shared__ float h0[64], h1[64];
    int w = t >> 5, lane = t & 31;
    for (int o = w; o < 192; o += 32) {
        const float* p = g_part + ((size_t)b * 192 + o) * NT2;
        float v = 0.f;
#pragma unroll
        for (int i = 0; i < 8; i++) v += p[lane + 32 * i];
#pragma unroll
        for (int off = 16; off; off >>= 1) v += __shfl_xor_sync(0xffffffffu, v, off);
        if (lane == 0) {
            float si = v * (1.0f / (246.0f * 246.0f));
            ss[o] = si;
            out[512 + b * 192 + o] = si;  // ssim_info after h
        }
    }
    __syncthreads();
    if (t < 64) {
        float acc = 0.f;
#pragma unroll
        for (int a = 0; a < 3; a++)
#pragma unroll
            for (int kh = 0; kh < 3; kh++) {
                int cc = t + kh - 1;
                if (cc >= 0 && cc < 64) acc = fmaf(ss[a * 64 + cc], conv_w[a * 3 + kh], acc);
            }
        h0[t] = fmaxf(acc, 0.f);
    }
    __syncthreads();
    if (t < 64) {
        float acc = b1[t];
#pragma unroll 8
        for (int k = 0; k < 64; k++) acc = fmaf(h0[k], w1[t * 64 + k], acc);
        h1[t] = fmaxf(acc, 0.f);
    }
    __syncthreads();
    if (t < 64) {
        float acc = b2[t];
#pragma unroll 8
        for (int k = 0; k < 64; k++) acc = fmaf(h1[k], w2[t * 64 + k], acc);
        out[b * 64 + t] = __fdividef(1.f, 1.f + __expf(-acc));
    }
}

// ---------------------------------------------------------------------------
extern "C" void kernel_launch(void* const* d_in, const int* in_sizes, int n_in,
                              void* d_out, int out_size) {
    const float* x = (const float*)d_in[0];
    const int* mask = (const int*)d_in[1];
    const float* conv_w = (const float*)d_in[2];
    const float* w1 = (const float*)d_in[3];
    const float* b1 = (const float*)d_in[4];
    const float* w2 = (const float*)d_in[5];
    const float* b2 = (const float*)d_in[6];
    float* out = (float*)d_out;

    cudaFuncSetAttribute(kC, cudaFuncAttributeMaxDynamicSharedMemorySize, SMEM_TOT);

    kA<<<dim3(HN / 4, BN), 256>>>(x, mask);
    kA2<<<BN, 256>>>();
    kC<<<dim3(16, 16, BN), 256, SMEM_TOT>>>(x, mask);
    kD<<<BN, 1024>>>(conv_w, w1, b1, w2, b2, out);
}